// round 6
// baseline (speedup 1.0000x reference)
#include <cuda_runtime.h>

// out[i,o,n] = 4-tap conv over x's last axis with channel mix, plus two circular
// rolls (n -> (n-1)%56 input remap; o=0 wrap correction on the second unfold arm).
//
// x: (1, 64, 56, 56) float32  -> x[j*3136 + n*56 + l]
// W: (64, 3, 2, 64)  float32  -> W[i*384 + k*128 + l2*64 + j]
// out: (1, 64, 56, 56) float32

#define NCH 64
#define LDIM 56
#define NSP 56
#define TPO 7   // o values per thread

__global__ __launch_bounds__(64, 8)
void shiftconv_kernel(const float* __restrict__ x,
                      const float* __restrict__ W,
                      float* __restrict__ out)
{
    // sX[j][c]: c = l + 2, guards c in {0,1,58,59} are zero (zero padding for taps)
    __shared__ float  sX[NCH][60];
    __shared__ float4 sV[NCH * 8];   // [j*8 + il] = (V_{-2}, V_{-1}, V_0, V_{+1})
    __shared__ float2 sC[NCH * 8];   // [j*8 + il] = (W[i,1,1,j], W[i,2,1,j])  (o=0 wrap fix)

    const int tid = threadIdx.x;
    const int n   = blockIdx.x;          // output column
    const int ig  = blockIdx.y;          // i-group of 8
    const int np  = (n + 55) % 56;       // n' = (n-1) mod 56 (final roll along axis 3)

    // ---- fill x slice (guard-padded, zero outside [0,56)) ----
    for (int idx = tid; idx < NCH * 60; idx += 64) {
        const int j = idx / 60;
        const int c = idx % 60;
        const int l = c - 2;
        float v = 0.0f;
        if (l >= 0 && l < LDIM) v = x[j * (NSP * LDIM) + np * LDIM + l];
        sX[j][c] = v;
    }

    // ---- weight transform: fold 6 taps -> 4 (V), keep 2 originals for o=0 wrap ----
    for (int p = tid; p < 8 * NCH; p += 64) {
        const int il = p & 7;
        const int j  = p >> 3;
        const int i  = ig * 8 + il;
        const float* wb = W + i * 384 + j;        // k stride 128, l2 stride 64
        const float w00 = wb[0],   w01 = wb[64];
        const float w10 = wb[128], w11 = wb[192];
        const float w20 = wb[256], w21 = wb[320];
        sV[j * 8 + il] = make_float4(w01, w00 + w11, w10 + w21, w20);
        sC[j * 8 + il] = make_float2(w11, w21);
    }
    __syncthreads();

    const int il  = tid & 7;             // i within group
    const int seg = tid >> 3;            // o segment (0..7)
    const int ob  = seg * TPO;           // o base

    float acc[TPO];
    #pragma unroll
    for (int t = 0; t < TPO; t++) acc[t] = 0.0f;

    #pragma unroll 4
    for (int j = 0; j < NCH; j++) {
        // window: padded idx ob..ob+9  ->  l = ob-2 .. ob+7  (o = ob..ob+6, d in [-2,1])
        const float* xr = &sX[j][ob];
        float xv[TPO + 3];
        #pragma unroll
        for (int t = 0; t < TPO + 3; t++) xv[t] = xr[t];

        const float4 v = sV[j * 8 + il];
        #pragma unroll
        for (int t = 0; t < TPO; t++)
            acc[t] = fmaf(xv[t],     v.x,
                     fmaf(xv[t + 1], v.y,
                     fmaf(xv[t + 2], v.z,
                     fmaf(xv[t + 3], v.w, acc[t]))));

        // o = 0 circular wrap on the second unfold arm:
        //   add  x[54]*W[i,0,1] + x[55]*W[i,1,1],  remove the wrong x[0]*W[i,2,1]
        if (seg == 0) {
            const float2 c = sC[j * 8 + il];
            acc[0] = fmaf(sX[j][56],  v.x,      // x[54] * W01  (W01 == V_{-2})
                     fmaf(sX[j][57],  c.x,      // x[55] * W11
                     fmaf(-sX[j][2],  c.y,      // -x[0] * W21
                          acc[0])));
        }
    }

    const int i = ig * 8 + il;
    float* op = out + i * (56 * 56) + ob * 56 + n;
    #pragma unroll
    for (int t = 0; t < TPO; t++) op[t * 56] = acc[t];
}

extern "C" void kernel_launch(void* const* d_in, const int* in_sizes, int n_in,
                              void* d_out, int out_size)
{
    const float* x = (const float*)d_in[0];
    const float* W = (const float*)d_in[1];
    float* out = (float*)d_out;
    (void)in_sizes; (void)n_in; (void)out_size;

    dim3 grid(56, 8);
    shiftconv_kernel<<<grid, 64>>>(x, W, out);
}

// round 8
// speedup vs baseline: 1.0173x; 1.0173x over previous
#include <cuda_runtime.h>

// out[i,o,n] = 4-tap conv over x's last axis with 64->64 channel mix, plus two
// circular rolls (n -> (n-1)%56 input remap; o=0 wrap correction on arm 2).
//
// x: (1, 64, 56, 56) float32  -> x[j*3136 + n*56 + l]
// W: (64, 3, 2, 64)  float32  -> W[i*384 + k*128 + l2*64 + j]
// out: (1, 64, 56, 56) float32
//
// Block = 256 threads: (il in 8 i's) x (seg in 8 o-segments) x (jq in 4 j-quarters).
// Each thread reduces 16 channels; 3 partials combined through smem.

#define NCH 64
#define LDIM 56
#define NSP 56
#define TPO 7   // o values per thread
#define JSPLIT 4
#define JPT (NCH / JSPLIT)   // 16 channels per thread

__global__ __launch_bounds__(256, 3)
void shiftconv_kernel(const float* __restrict__ x,
                      const float* __restrict__ W,
                      float* __restrict__ out)
{
    // sX[j][c]: c = l + 2, guards c in {0,1,58,59} are zero (tap zero-padding)
    __shared__ float  sX[NCH][60];
    __shared__ float4 sV[NCH * 8];            // [j*8 + il] = (V_{-2}, V_{-1}, V_0, V_{+1})
    __shared__ float2 sC[NCH * 8];            // [j*8 + il] = (W[i,1,1,j], W[i,2,1,j])
    __shared__ float  sP[JSPLIT - 1][8][8][8]; // partials [jq-1][seg][il][t] (t padded to 8)

    const int tid = threadIdx.x;
    const int n   = blockIdx.x;          // output column
    const int ig  = blockIdx.y;          // i-group of 8
    const int np  = (n + 55) % 56;       // n' = (n-1) mod 56 (final roll along axis 3)

    // ---- fill x slice (guard-padded, zero outside [0,56)) ----
    for (int idx = tid; idx < NCH * 60; idx += 256) {
        const int j = idx / 60;
        const int c = idx % 60;
        const int l = c - 2;
        float v = 0.0f;
        if (l >= 0 && l < LDIM) v = x[j * (NSP * LDIM) + np * LDIM + l];
        sX[j][c] = v;
    }

    // ---- weight transform: fold 6 taps -> 4 (V), keep 2 originals for o=0 wrap ----
    for (int p = tid; p < 8 * NCH; p += 256) {
        const int il = p & 7;
        const int j  = p >> 3;
        const int i  = ig * 8 + il;
        const float* wb = W + i * 384 + j;        // k stride 128, l2 stride 64
        const float w00 = wb[0],   w01 = wb[64];
        const float w10 = wb[128], w11 = wb[192];
        const float w20 = wb[256], w21 = wb[320];
        sV[j * 8 + il] = make_float4(w01, w00 + w11, w10 + w21, w20);
        sC[j * 8 + il] = make_float2(w11, w21);
    }
    __syncthreads();

    const int il  = tid & 7;             // i within group
    const int seg = (tid >> 3) & 7;      // o segment (0..7)
    const int jq  = tid >> 6;            // j quarter (0..3)
    const int ob  = seg * TPO;           // o base
    const int j0  = jq * JPT;

    float acc[TPO];
    #pragma unroll
    for (int t = 0; t < TPO; t++) acc[t] = 0.0f;

    #pragma unroll 4
    for (int jj = 0; jj < JPT; jj++) {
        const int j = j0 + jj;
        // window: padded idx ob..ob+9  ->  l = ob-2 .. ob+7  (o = ob..ob+6, d in [-2,1])
        const float* xr = &sX[j][ob];
        float xv[TPO + 3];
        #pragma unroll
        for (int t = 0; t < TPO + 3; t++) xv[t] = xr[t];

        const float4 v = sV[j * 8 + il];
        #pragma unroll
        for (int t = 0; t < TPO; t++)
            acc[t] = fmaf(xv[t],     v.x,
                     fmaf(xv[t + 1], v.y,
                     fmaf(xv[t + 2], v.z,
                     fmaf(xv[t + 3], v.w, acc[t]))));

        // o = 0 circular wrap on the second unfold arm:
        //   add x[54]*W[i,0,1] + x[55]*W[i,1,1], remove the wrong x[0]*W[i,2,1]
        if (seg == 0) {
            const float2 c = sC[j * 8 + il];
            acc[0] = fmaf(sX[j][56],  v.x,      // x[54] * W01  (W01 == V_{-2})
                     fmaf(sX[j][57],  c.x,      // x[55] * W11
                     fmaf(-sX[j][2],  c.y,      // -x[0] * W21
                          acc[0])));
        }
    }

    // ---- combine the 4 j-partials ----
    if (jq > 0) {
        #pragma unroll
        for (int t = 0; t < TPO; t++) sP[jq - 1][seg][il][t] = acc[t];
    }
    __syncthreads();

    if (jq == 0) {
        #pragma unroll
        for (int t = 0; t < TPO; t++)
            acc[t] += sP[0][seg][il][t] + sP[1][seg][il][t] + sP[2][seg][il][t];

        const int i = ig * 8 + il;
        float* op = out + i * (56 * 56) + ob * 56 + n;
        #pragma unroll
        for (int t = 0; t < TPO; t++) op[t * 56] = acc[t];
    }
}

extern "C" void kernel_launch(void* const* d_in, const int* in_sizes, int n_in,
                              void* d_out, int out_size)
{
    const float* x = (const float*)d_in[0];
    const float* W = (const float*)d_in[1];
    float* out = (float*)d_out;
    (void)in_sizes; (void)n_in; (void)out_size;

    dim3 grid(56, 8);
    shiftconv_kernel<<<grid, 256>>>(x, W, out);
}

// round 9
// speedup vs baseline: 1.3692x; 1.3459x over previous
#include <cuda_runtime.h>

// out[i,o,n] = 4-tap conv over x's last axis with 64->64 channel mix, plus two
// circular rolls (n -> (n-1)%56 input remap; o=0 wrap correction on arm 2).
//
// x: (1, 64, 56, 56) float32  -> x[j*3136 + n*56 + l]
// W: (64, 3, 2, 64)  float32  -> W[i*384 + k*128 + l2*64 + j]
// out: (1, 64, 56, 56) float32
//
// Block = 224 threads: (il2 in 4 i-pairs) x (seg in 7 o-octets) x (jq in 8 j-slices).
// Each thread: 2 i's x 8 o's over 8 channels; vectorized LDS.128 x-window reuse.

#define NROW 60   // c = l + 2; guards c in {0,1,58,59} are zero

__global__ __launch_bounds__(224, 3)
void shiftconv_kernel(const float* __restrict__ x,
                      const float* __restrict__ W,
                      float* __restrict__ out)
{
    __shared__ __align__(16) float  sX[64][NROW];
    __shared__ __align__(16) float4 sV[64][9];   // [j][il] = (V-2, V-1, V0, V+1), padded row
    __shared__ __align__(16) float2 sC[64][8];   // [j][il] = (W[i,1,1,j], W[i,2,1,j])
    __shared__ __align__(16) char   uni[17920];  // phase1: raw W slice (12288B); tail: partials

    float* sW = (float*)uni;                          // [3072] = W[ig*8 .. +8) rows
    float (*sP)[28][20] = (float (*)[28][20])uni;     // [jq][seg*4+il2][a*8+t], pad 16->20

    const int tid = threadIdx.x;
    const int n   = blockIdx.x;          // output column
    const int ig  = blockIdx.y;          // i-group of 8
    const int np  = (n + 55) % 56;       // (n-1) mod 56  (final roll along axis 3)

    // ---- phase 1a: x slice -> sX interior, float4 loads (896 = 224*4 exactly) ----
    const float4* X4 = (const float4*)x;
    #pragma unroll
    for (int q = 0; q < 4; q++) {
        const int f = tid + 224 * q;           // 0..895
        const int j = f / 14, r = f % 14;
        const float4 g = X4[j * 784 + np * 14 + r];
        float* d = &sX[j][2 + 4 * r];
        d[0] = g.x; d[1] = g.y; d[2] = g.z; d[3] = g.w;
    }
    // guards: c in {0,1,58,59} = 0 for all 64 j
    for (int p = tid; p < 256; p += 224) {
        const int j = p >> 2, g = p & 3;
        sX[j][(g & 1) + (g >> 1) * 58] = 0.0f;
    }
    // ---- phase 1b: raw W slice -> smem (contiguous float4, 768 vec loads) ----
    const float4* W4 = (const float4*)W;
    for (int f = tid; f < 768; f += 224)
        ((float4*)sW)[f] = W4[ig * 768 + f];
    __syncthreads();

    // ---- phase 2: weight transform (fold 6 taps -> 4, keep 2 for o=0 wrap) ----
    for (int p = tid; p < 512; p += 224) {
        const int il = p >> 6, j = p & 63;
        const float* wb = sW + il * 384 + j;   // k stride 128, l2 stride 64
        const float w00 = wb[0],   w01 = wb[64];
        const float w10 = wb[128], w11 = wb[192];
        const float w20 = wb[256], w21 = wb[320];
        sV[j][il] = make_float4(w01, w00 + w11, w10 + w21, w20);
        sC[j][il] = make_float2(w11, w21);
    }
    __syncthreads();

    // ---- mainloop ----
    const int il2 = tid & 3;             // i-pair index (i = ig*8 + 2*il2 + {0,1})
    const int seg = (tid >> 2) % 7;      // o octet (0..6)
    const int jq  = tid / 28;            // j slice (0..7)
    const int ob  = seg * 8;
    const int j0  = jq * 8;

    float a0[8], a1[8];
    #pragma unroll
    for (int t = 0; t < 8; t++) { a0[t] = 0.0f; a1[t] = 0.0f; }

    #pragma unroll
    for (int jj = 0; jj < 8; jj++) {
        const int j = j0 + jj;
        // window c = ob..ob+11 (o = ob..ob+7, taps d in [-2,1]) : 3 aligned float4
        const float4* xr = (const float4*)&sX[j][ob];
        const float4 xa = xr[0], xb = xr[1], xc = xr[2];
        const float xv[12] = {xa.x, xa.y, xa.z, xa.w, xb.x, xb.y, xb.z, xb.w,
                              xc.x, xc.y, xc.z, xc.w};
        const float4 v0 = sV[j][il2 * 2];
        const float4 v1 = sV[j][il2 * 2 + 1];
        #pragma unroll
        for (int t = 0; t < 8; t++) {
            a0[t] = fmaf(xv[t],     v0.x,
                    fmaf(xv[t + 1], v0.y,
                    fmaf(xv[t + 2], v0.z,
                    fmaf(xv[t + 3], v0.w, a0[t]))));
            a1[t] = fmaf(xv[t],     v1.x,
                    fmaf(xv[t + 1], v1.y,
                    fmaf(xv[t + 2], v1.z,
                    fmaf(xv[t + 3], v1.w, a1[t]))));
        }
        // o = 0 wrap on the second unfold arm:
        // add x[54]*W[i,0,1] + x[55]*W[i,1,1], remove the wrong x[0]*W[i,2,1]
        if (seg == 0) {
            const float2 c0 = sC[j][il2 * 2];
            const float2 c1 = sC[j][il2 * 2 + 1];
            const float x54 = sX[j][56], x55 = sX[j][57], x00 = sX[j][2];
            a0[0] = fmaf(x54, v0.x, fmaf(x55, c0.x, fmaf(-x00, c0.y, a0[0])));
            a1[0] = fmaf(x54, v1.x, fmaf(x55, c1.x, fmaf(-x00, c1.y, a1[0])));
        }
    }

    // ---- park partials (sW region is dead since phase 2 ended at the barrier) ----
    {
        float4* pr = (float4*)&sP[jq][seg * 4 + il2][0];
        pr[0] = make_float4(a0[0], a0[1], a0[2], a0[3]);
        pr[1] = make_float4(a0[4], a0[5], a0[6], a0[7]);
        pr[2] = make_float4(a1[0], a1[1], a1[2], a1[3]);
        pr[3] = make_float4(a1[4], a1[5], a1[6], a1[7]);
    }
    __syncthreads();

    // ---- fully parallel reduction + store: 448 outputs, 2 per thread ----
    #pragma unroll
    for (int q2 = 0; q2 < 2; q2++) {
        const int q     = tid + 224 * q2;    // 0..447
        const int i_loc = q & 7;
        const int o     = q >> 3;
        const int row   = (o >> 3) * 4 + (i_loc >> 1);
        const int col   = (i_loc & 1) * 8 + (o & 7);
        float s = 0.0f;
        #pragma unroll
        for (int sj = 0; sj < 8; sj++) s += sP[sj][row][col];
        out[(ig * 8 + i_loc) * 3136 + o * 56 + n] = s;
    }
}

extern "C" void kernel_launch(void* const* d_in, const int* in_sizes, int n_in,
                              void* d_out, int out_size)
{
    const float* x = (const float*)d_in[0];
    const float* W = (const float*)d_in[1];
    float* out = (float*)d_out;
    (void)in_sizes; (void)n_in; (void)out_size;

    dim3 grid(56, 8);
    shiftconv_kernel<<<grid, 224>>>(x, W, out);
}

// round 10
// speedup vs baseline: 1.4018x; 1.0238x over previous
#include <cuda_runtime.h>

// out[i,o,n] = 4-tap conv over x's last axis with 64->64 channel mix, plus two
// circular rolls (n -> (n-1)%56 input remap; o=0 wrap correction on arm 2).
//
// x: (1, 64, 56, 56) float32  -> x[j*3136 + n*56 + l]
// W: (64, 3, 2, 64)  float32  -> W[i*384 + k*128 + l2*64 + j]
// out: (1, 64, 56, 56) float32
//
// Block = 224 threads: (il2 in 4 i-pairs) x (seg in 7 o-octets) x (jq in 8 j-slices).
// Each thread: 2 i's x 8 o's over 8 channels; vectorized LDS.128 x-window reuse.
// occ=4 -> 148*4 = 592 slots >= 448 blocks: single wave, no quantization tail.

#define NROW 60   // c = l + 2; guards c in {0,1,58,59} are zero

__global__ __launch_bounds__(224, 4)
void shiftconv_kernel(const float* __restrict__ x,
                      const float* __restrict__ W,
                      float* __restrict__ out)
{
    __shared__ __align__(16) float  sX[64][NROW];
    __shared__ __align__(16) float4 sV[64][9];   // [j][il] = (V-2, V-1, V0, V+1), padded row
    __shared__ __align__(16) float2 sC[64][8];   // [j][il] = (W[i,1,1,j], W[i,2,1,j])
    __shared__ __align__(16) char   uni[17920];  // phase1: raw W slice (12288B); tail: partials

    float* sW = (float*)uni;                          // [3072] = W[ig*8 .. +8) rows
    float (*sP)[28][20] = (float (*)[28][20])uni;     // [jq][seg*4+il2][a*8+t], pad 16->20

    const int tid = threadIdx.x;
    const int n   = blockIdx.x;          // output column
    const int ig  = blockIdx.y;          // i-group of 8
    const int np  = (n + 55) % 56;       // (n-1) mod 56  (final roll along axis 3)

    // ---- phase 1a: x slice -> sX interior, float4 loads (896 = 224*4 exactly) ----
    const float4* X4 = (const float4*)x;
    #pragma unroll
    for (int q = 0; q < 4; q++) {
        const int f = tid + 224 * q;           // 0..895
        const int j = f / 14, r = f % 14;
        const float4 g = X4[j * 784 + np * 14 + r];
        float* d = &sX[j][2 + 4 * r];
        d[0] = g.x; d[1] = g.y; d[2] = g.z; d[3] = g.w;
    }
    // guards: c in {0,1,58,59} = 0 for all 64 j
    for (int p = tid; p < 256; p += 224) {
        const int j = p >> 2, g = p & 3;
        sX[j][(g & 1) + (g >> 1) * 58] = 0.0f;
    }
    // ---- phase 1b: raw W slice -> smem (contiguous float4, 768 vec loads) ----
    const float4* W4 = (const float4*)W;
    for (int f = tid; f < 768; f += 224)
        ((float4*)sW)[f] = W4[ig * 768 + f];
    __syncthreads();

    // ---- phase 2: weight transform (fold 6 taps -> 4, keep 2 for o=0 wrap) ----
    for (int p = tid; p < 512; p += 224) {
        const int il = p >> 6, j = p & 63;
        const float* wb = sW + il * 384 + j;   // k stride 128, l2 stride 64
        const float w00 = wb[0],   w01 = wb[64];
        const float w10 = wb[128], w11 = wb[192];
        const float w20 = wb[256], w21 = wb[320];
        sV[j][il] = make_float4(w01, w00 + w11, w10 + w21, w20);
        sC[j][il] = make_float2(w11, w21);
    }
    __syncthreads();

    // ---- mainloop ----
    const int il2 = tid & 3;             // i-pair index (i = ig*8 + 2*il2 + {0,1})
    const int seg = (tid >> 2) % 7;      // o octet (0..6)
    const int jq  = tid / 28;            // j slice (0..7)
    const int ob  = seg * 8;
    const int j0  = jq * 8;

    float a0[8], a1[8];
    #pragma unroll
    for (int t = 0; t < 8; t++) { a0[t] = 0.0f; a1[t] = 0.0f; }

    #pragma unroll
    for (int jj = 0; jj < 8; jj++) {
        const int j = j0 + jj;
        // window c = ob..ob+11 (o = ob..ob+7, taps d in [-2,1]) : 3 aligned float4
        const float4* xr = (const float4*)&sX[j][ob];
        const float4 xa = xr[0], xb = xr[1], xc = xr[2];
        const float xv[12] = {xa.x, xa.y, xa.z, xa.w, xb.x, xb.y, xb.z, xb.w,
                              xc.x, xc.y, xc.z, xc.w};
        const float4 v0 = sV[j][il2 * 2];
        const float4 v1 = sV[j][il2 * 2 + 1];
        #pragma unroll
        for (int t = 0; t < 8; t++) {
            a0[t] = fmaf(xv[t],     v0.x,
                    fmaf(xv[t + 1], v0.y,
                    fmaf(xv[t + 2], v0.z,
                    fmaf(xv[t + 3], v0.w, a0[t]))));
            a1[t] = fmaf(xv[t],     v1.x,
                    fmaf(xv[t + 1], v1.y,
                    fmaf(xv[t + 2], v1.z,
                    fmaf(xv[t + 3], v1.w, a1[t]))));
        }
        // o = 0 wrap on the second unfold arm:
        // add x[54]*W[i,0,1] + x[55]*W[i,1,1], remove the wrong x[0]*W[i,2,1]
        if (seg == 0) {
            const float2 c0 = sC[j][il2 * 2];
            const float2 c1 = sC[j][il2 * 2 + 1];
            const float x54 = sX[j][56], x55 = sX[j][57], x00 = sX[j][2];
            a0[0] = fmaf(x54, v0.x, fmaf(x55, c0.x, fmaf(-x00, c0.y, a0[0])));
            a1[0] = fmaf(x54, v1.x, fmaf(x55, c1.x, fmaf(-x00, c1.y, a1[0])));
        }
    }

    // ---- park partials (sW region is dead since phase 2 ended at the barrier) ----
    __syncthreads();   // ensure all phase-2 reads of sW are done before overwrite
    {
        float4* pr = (float4*)&sP[jq][seg * 4 + il2][0];
        pr[0] = make_float4(a0[0], a0[1], a0[2], a0[3]);
        pr[1] = make_float4(a0[4], a0[5], a0[6], a0[7]);
        pr[2] = make_float4(a1[0], a1[1], a1[2], a1[3]);
        pr[3] = make_float4(a1[4], a1[5], a1[6], a1[7]);
    }
    __syncthreads();

    // ---- fully parallel reduction + store: 448 outputs, 2 per thread ----
    #pragma unroll
    for (int q2 = 0; q2 < 2; q2++) {
        const int q     = tid + 224 * q2;    // 0..447
        const int i_loc = q & 7;
        const int o     = q >> 3;
        const int row   = (o >> 3) * 4 + (i_loc >> 1);
        const int col   = (i_loc & 1) * 8 + (o & 7);
        float s = 0.0f;
        #pragma unroll
        for (int sj = 0; sj < 8; sj++) s += sP[sj][row][col];
        out[(ig * 8 + i_loc) * 3136 + o * 56 + n] = s;
    }
}

extern "C" void kernel_launch(void* const* d_in, const int* in_sizes, int n_in,
                              void* d_out, int out_size)
{
    const float* x = (const float*)d_in[0];
    const float* W = (const float*)d_in[1];
    float* out = (float*)d_out;
    (void)in_sizes; (void)n_in; (void)out_size;

    dim3 grid(56, 8);
    shiftconv_kernel<<<grid, 224>>>(x, W, out);
}